// round 15
// baseline (speedup 1.0000x reference)
#include <cuda_runtime.h>
#include <math.h>

#define ND 4096
#define MM 8192
#define DE 256
#define TOPK 8

#define OBJ_THR   0.3f
#define INIT_THR  0.7f
#define MATCH_THR 0.5f
#define IOU_BACK  0.3f
#define IOU_CLASS 0.7f
#define CEXP      32.0f
#define FULLM     0xFFFFFFFFu

#define BM 128
#define BN 128
#define BK 16
#define NSEG (ND / BM)   // 32 block-rows max

// ---------------- scratch (device globals; no allocation allowed) ----------
static __device__ float    g_feats[(size_t)ND * MM];   // stores E = exp(f - 32)
static __device__ int      g_order[ND];
static __device__ float    g_scores_s[ND];
static __device__ int      g_cls_s[ND];
static __device__ float4   g_boxes_s[ND];
static __device__ float    g_area_s[ND];
static __device__ float    g_emb_s[ND * DE];
static __device__ float    g_embc[ND * DE];            // compacted embeddings
static __device__ int      g_bad[ND];
static __device__ int      g_valid[ND];
static __device__ int      g_vpos[ND];                 // sorted row -> compact row
static __device__ int      g_vrow[ND];                 // compact row -> sorted row
static __device__ int      g_nvalid;
static __device__ float    g_colpart[NSEG][MM];        // per-blockrow col sums of E
static __device__ float    g_colhalf[MM];              // 0.5 / colsum
static __device__ float    g_topv[ND][TOPK];
static __device__ int      g_topi[ND][TOPK];

// ---------------- 1. argsort(-scores): parallel rank-by-counting ------------
__global__ void rank_kernel(const float* __restrict__ scores) {
    __shared__ unsigned long long sk[ND];
    int t = threadIdx.x;                    // 256
    int me = blockIdx.x * 256 + t;
    for (int i = t; i < ND; i += 256) {
        unsigned u = __float_as_uint(scores[i]);
        u ^= (u & 0x80000000u) ? 0xFFFFFFFFu : 0x80000000u;
        u = ~u;
        sk[i] = ((unsigned long long)u << 32) | (unsigned)i;
    }
    __syncthreads();
    unsigned long long mykey = sk[me];
    int rank = 0;
#pragma unroll 8
    for (int j = 0; j < ND; j++)
        rank += (sk[j] < mykey) ? 1 : 0;
    g_order[rank] = me;
}

// ---------------- 2. gather sorted views (+ areas) ---------------------------
__global__ void gather_kernel(const float* __restrict__ det,
                              const float* __restrict__ scores,
                              const int*   __restrict__ cls,
                              const float* __restrict__ emb) {
    int i = blockIdx.x;
    int o = g_order[i];
    if (threadIdx.x == 0) {
        g_scores_s[i] = scores[o];
        g_cls_s[i]    = cls[o];
        float4 b;
        b.x = det[o * 4 + 0]; b.y = det[o * 4 + 1];
        b.z = det[o * 4 + 2]; b.w = det[o * 4 + 3];
        g_boxes_s[i] = b;
        g_area_s[i] = fmaxf(b.z - b.x, 0.f) * fmaxf(b.w - b.y, 0.f);
    }
    for (int k = threadIdx.x; k < DE; k += blockDim.x)
        g_emb_s[i * DE + k] = emb[o * DE + k];
}

// ------ 3. NMS: 4 subwarps per detection, disjoint j-quarters, smem OR ------
// Each subwarp scans j in {s*128 + u*32 + lane : j0 += 512} with its own
// early exit -> serial ballot chain max 8 (was 32). Final OR across subwarps.
__global__ void nms_kernel() {
    __shared__ int flags[2];
    int local = threadIdx.x >> 7;           // det within block: 0..1
    int sub   = (threadIdx.x >> 5) & 3;     // subwarp 0..3
    int lane  = threadIdx.x & 31;
    int i = blockIdx.x * 2 + local;         // 2048 blocks * 2 = 4096 dets
    if (threadIdx.x < 2) flags[threadIdx.x] = 0;
    __syncthreads();

    float4 bx = g_boxes_s[i];
    float  si = g_scores_s[i];
    float  thr = (si < OBJ_THR) ? IOU_BACK : IOU_CLASS;
    float  area_i = g_area_s[i];
    bool bad = false;
    for (int j0 = sub * 128; j0 < i; j0 += 512) {
        bool ex = false;
#pragma unroll
        for (int u = 0; u < 4; u++) {
            int j = j0 + u * 32 + lane;
            if (j < i) {
                float4 bb = g_boxes_s[j];
                float  aj = g_area_s[j];
                float lx = fmaxf(bx.x, bb.x), ly = fmaxf(bx.y, bb.y);
                float rx = fminf(bx.z, bb.z), ry = fminf(bx.w, bb.w);
                float w = fmaxf(rx - lx, 0.f), h = fmaxf(ry - ly, 0.f);
                float inter = w * h;
                float denom = fmaxf(area_i + aj - inter, 1e-6f);
                ex |= (inter / denom > thr);   // exact division (reference semantics)
            }
        }
        if (__any_sync(FULLM, ex)) { bad = true; break; }
    }
    if (lane == 0 && bad) atomicOr(&flags[local], 1);
    __syncthreads();
    if ((threadIdx.x & 127) == 0) g_bad[i] = flags[local];
}

// ------- 4. compaction (prefix sum) + fused embedding compaction ------------
__global__ void compact_kernel() {
    __shared__ int s[1024];
    __shared__ int snv;
    int t = threadIdx.x;
    int v[4], cnt = 0;
#pragma unroll
    for (int k = 0; k < 4; k++) {
        v[k] = g_bad[t * 4 + k] ? 0 : 1;
        cnt += v[k];
    }
    s[t] = cnt;
    __syncthreads();
    for (int off = 1; off < 1024; off <<= 1) {
        int val = s[t];
        if (t >= off) val += s[t - off];
        __syncthreads();
        s[t] = val;
        __syncthreads();
    }
    int base = s[t] - cnt;
#pragma unroll
    for (int k = 0; k < 4; k++) {
        int i = t * 4 + k;
        g_valid[i] = v[k];
        g_vpos[i] = base;
        if (v[k]) { g_vrow[base] = i; base++; }
    }
    if (t == 1023) { g_nvalid = s[1023]; snv = s[1023]; }
    __syncthreads();
    // fused embcompact: copy nv rows (64 float4 each)
    int nv = snv;
    for (int idx = t; idx < nv * 64; idx += 1024) {
        int p = idx >> 6, k = idx & 63;
        int r = g_vrow[p];
        ((float4*)&g_embc[p * DE])[k] = ((const float4*)&g_emb_s[r * DE])[k];
    }
}

// ------- 5. SGEMM; epilogue: E = exp(f-32) + col sums -----------------------
__global__ void sgemm_kernel(const float* __restrict__ B) {
    int nv = g_nvalid;
    int bm = blockIdx.y * BM;
    if (bm >= nv) return;
    __shared__ float As[BK][BM + 4];
    __shared__ float Bs[BK][BN + 4];
    __shared__ float s_part[16][BN];
    int bn = blockIdx.x * BN;
    int tid = threadIdx.x;   // 256
    int ti = tid / 16;
    int tr = ti * 8;
    int tc = (tid % 16) * 8;

    float acc[8][8];
#pragma unroll
    for (int i = 0; i < 8; i++)
#pragma unroll
        for (int j = 0; j < 8; j++) acc[i][j] = 0.f;

    int lrow = tid / 4;
    int lc4  = (tid % 4) * 4;

    for (int k0 = 0; k0 < DE; k0 += BK) {
        __syncthreads();
#pragma unroll
        for (int l = 0; l < 2; l++) {
            int row = l * 64 + lrow;
            float4 va = *(const float4*)&g_embc[(bm + row) * DE + k0 + lc4];
            As[lc4 + 0][row] = va.x; As[lc4 + 1][row] = va.y;
            As[lc4 + 2][row] = va.z; As[lc4 + 3][row] = va.w;
            float4 vb = *(const float4*)&B[(size_t)(bn + row) * DE + k0 + lc4];
            Bs[lc4 + 0][row] = vb.x; Bs[lc4 + 1][row] = vb.y;
            Bs[lc4 + 2][row] = vb.z; Bs[lc4 + 3][row] = vb.w;
        }
        __syncthreads();
#pragma unroll
        for (int kk = 0; kk < BK; kk++) {
            float a[8], b[8];
#pragma unroll
            for (int i = 0; i < 8; i++) a[i] = As[kk][tr + i];
#pragma unroll
            for (int j = 0; j < 8; j++) b[j] = Bs[kk][tc + j];
#pragma unroll
            for (int i = 0; i < 8; i++)
#pragma unroll
                for (int j = 0; j < 8; j++) acc[i][j] = fmaf(a[i], b[j], acc[i][j]);
        }
    }
#pragma unroll
    for (int i = 0; i < 8; i++) {
#pragma unroll
        for (int j = 0; j < 8; j++) acc[i][j] = __expf(acc[i][j] - CEXP);
        float* dst = &g_feats[(size_t)(bm + tr + i) * MM + bn + tc];
        *(float4*)dst       = make_float4(acc[i][0], acc[i][1], acc[i][2], acc[i][3]);
        *(float4*)(dst + 4) = make_float4(acc[i][4], acc[i][5], acc[i][6], acc[i][7]);
    }
#pragma unroll
    for (int j = 0; j < 8; j++) {
        float ps = 0.f;
#pragma unroll
        for (int i = 0; i < 8; i++) {
            if (bm + tr + i < nv) ps += acc[i][j];
        }
        s_part[ti][tc + j] = ps;
    }
    __syncthreads();
    if (tid < BN) {
        float s = 0.f;
#pragma unroll
        for (int k = 0; k < 16; k++) s += s_part[k][tid];
        g_colpart[blockIdx.y][bn + tid] = s;
    }
}

// ---------------- 6. merge column partials (plain sums) ---------------------
__global__ void colmerge_kernel() {
    int c = blockIdx.x * 256 + threadIdx.x;
    int nseg = (g_nvalid + BM - 1) / BM;
    float s = 0.f;
    for (int seg = 0; seg < nseg; seg++) s += g_colpart[seg][c];
    g_colhalf[c] = 0.5f / s;
}

// ---------------- 7. sims + row sum + top-8 (single pass, local top-9) ------
__global__ void simsrow_kernel(const int* __restrict__ memo_cls,
                               float* __restrict__ out) {
    __shared__ float srow[MM];
    __shared__ float s_red[256];
    __shared__ int   s_ri[256];
    __shared__ float sv[9 * 256];
    __shared__ int   si[9 * 256];
    int r = blockIdx.x, t = threadIdx.x;
    float* orow = out + 2 * ND + (size_t)r * MM;
    if (!g_valid[r]) {
        float4 z = make_float4(0.f, 0.f, 0.f, 0.f);
        float4* o4 = (float4*)orow;
        for (int j = t; j < MM / 4; j += 256) o4[j] = z;
        if (t < TOPK) { g_topv[r][t] = 0.f; g_topi[r][t] = 0; }
        return;
    }
    int v = g_vpos[r];
    const float4* f4 = (const float4*)(g_feats + (size_t)v * MM);
    float p0 = 0.f, p1 = 0.f;
#pragma unroll
    for (int it = 0; it < 8; it++) {
        int idx = t + it * 256;
        float4 x = f4[idx];
        ((float4*)srow)[idx] = x;
        p0 += x.x + x.z;
        p1 += x.y + x.w;
    }
    s_red[t] = p0 + p1;
    __syncthreads();
    for (int o = 128; o; o >>= 1) {
        if (t < o) s_red[t] += s_red[t + o];
        __syncthreads();
    }
    float hr = 0.5f / s_red[0];
    int clsr = g_cls_s[r];
    __syncthreads();

    float lv[9]; int li[9];
#pragma unroll
    for (int k = 0; k < 9; k++) { lv[k] = -1.f; li[k] = MM; }
    for (int j = t; j < MM; j += 256) {
        float E = srow[j];
        float hc = g_colhalf[j];
        float x = (memo_cls[j] == clsr) ? E * (hr + hc) : 0.f;
        orow[j] = x;
        if (x > lv[8]) {
            lv[8] = x; li[8] = j;
#pragma unroll
            for (int p = 8; p > 0; p--) {
                if (lv[p] > lv[p - 1]) {
                    float tv = lv[p]; lv[p] = lv[p - 1]; lv[p - 1] = tv;
                    int   tj = li[p]; li[p] = li[p - 1]; li[p - 1] = tj;
                }
            }
        }
    }
#pragma unroll
    for (int k = 0; k < 9; k++) { sv[k * 256 + t] = lv[k]; si[k * 256 + t] = li[k]; }
    __syncthreads();

    int h = 0;
    for (int k = 0; k < TOPK; k++) {
        float cv = (h < 9) ? sv[h * 256 + t] : -1.f;
        int   ci = (h < 9) ? si[h * 256 + t] : MM;
        s_red[t] = cv; s_ri[t] = ci;
        __syncthreads();
        for (int o = 128; o; o >>= 1) {
            if (t < o) {
                float ov = s_red[t + o]; int oi = s_ri[t + o];
                if (ov > s_red[t] || (ov == s_red[t] && oi < s_ri[t])) {
                    s_red[t] = ov; s_ri[t] = oi;
                }
            }
            __syncthreads();
        }
        float bv = s_red[0]; int bi = s_ri[0];
        if (t == 0) { g_topv[r][k] = bv; g_topi[r][k] = bi; }
        __syncthreads();
        if (cv == bv && ci == bi) h++;
    }
}

// -------- 8. greedy: parallel prefetch + prefix-safe parallel commits -------
#define GREEDY_SMEM (ND * 8 * 4 + ND * 4 + (MM / 32) * 4 + ND * 2 + ND)

__global__ void greedy_kernel(const int* __restrict__ memo_track,
                              const int* __restrict__ num_tracks_ptr,
                              float* __restrict__ out) {
    extern __shared__ unsigned char dsm[];
    unsigned*       s_cand = (unsigned*)dsm;
    int*            s_idv  = (int*)(s_cand + ND * 8);
    unsigned*       tk     = (unsigned*)(s_idv + ND);
    unsigned short* s_pk   = (unsigned short*)(tk + MM / 32);
    unsigned char*  s_cnt  = (unsigned char*)(s_pk + ND);
    int t = threadIdx.x;

    for (int e = t; e < ND * 8; e += 1024) {
        int r = e >> 3, k = e & 7;
        float v = g_topv[r][k];
        unsigned w = 0xFFFFFFFFu;
        if (v > MATCH_THR) {
            int ind = g_topi[r][k];
            int trk = memo_track[ind];
            int it = (trk > -1) ? 1 : 0;
            w = (unsigned)ind | ((unsigned)it << 13) |
                ((unsigned)(it ? trk : 0) << 14);
        }
        s_cand[e] = w;
    }
    for (int i = t; i < MM / 32; i += 1024) tk[i] = 0u;
    for (int r = t; r < ND; r += 1024) {
        float sc = g_scores_s[r];
        s_pk[r] = (unsigned short)((g_valid[r] & 1) |
                  ((sc > OBJ_THR) ? 2 : 0) | ((sc > INIT_THR) ? 4 : 0));
        int c = 0;
        while (c < 8 && g_topv[r][c] > MATCH_THR) c++;
        s_cnt[r] = (unsigned char)c;
    }
    __syncthreads();

    if (t < 32) {
        int lane = t;
        const float* sims = out + 2 * ND;

        for (int cch = 0; cch < ND / 32; cch++) {
            int r = cch * 32 + lane;
            int cnt = s_cnt[r];
            int idx = 0;
            int idv = -1;
            bool done = (cnt == 0);

            while (true) {
                unsigned unc = __ballot_sync(FULLM, !done);
                if (!unc) break;

                int action = 0;
                int P = 0x4000 + lane;
                int myind = -1, mytid = 0, myit = 0;
                if (!done) {
                    while (idx < cnt) {
                        unsigned w = s_cand[r * 8 + idx];
                        int ind = (int)(w & 0x1FFFu);
                        if ((tk[ind >> 5] >> (ind & 31)) & 1u) idx++;
                        else {
                            myind = ind;
                            myit = (int)((w >> 13) & 1u);
                            mytid = (int)(w >> 14);
                            break;
                        }
                    }
                    if (idx >= cnt) {
                        if (cnt == 8) action = 4;
                        else { action = 1; idv = -1; }
                    } else {
                        P = myind;
                    }
                }
                unsigned grp = __match_any_sync(FULLM, P);
                unsigned pickm = __ballot_sync(FULLM, !done && action == 0);
                unsigned strongm = __ballot_sync(FULLM,
                                                 !done && ((s_pk[r] >> 1) & 1));
                if (!done && action == 0) {
                    if (!myit) { action = 1; idv = -2; }
                    else {
                        unsigned g = grp & pickm;
                        unsigned sg = g & strongm;
                        if (sg == 0) { action = 1; idv = -1; }
                        else {
                            int s = __ffs(sg) - 1;
                            if (lane < s)       { action = 1; idv = -1; }
                            else if (lane == s) { action = 2; idv = mytid; }
                            else                  action = 3;
                        }
                    }
                }
                unsigned deferm = __ballot_sync(FULLM,
                                                !done && (action == 3 || action == 4));
                int fb = deferm ? (__ffs(deferm) - 1) : 32;
                bool dep = (!done && (action == 1 || action == 2) &&
                            myind >= 0 && myit);
                if (dep && lane > fb) action = 3;

                if (!done && (action == 1 || action == 2)) {
                    if (action == 2)
                        atomicOr(&tk[myind >> 5], 1u << (myind & 31));
                    done = true;
                }
                __syncwarp(FULLM);

                unsigned unc2 = __ballot_sync(FULLM, !done);
                while (unc2) {
                    int low = __ffs(unc2) - 1;
                    int lact = __shfl_sync(FULLM, action, low);
                    if (lact != 4) break;
                    int rr = cch * 32 + low;
                    const float* row = sims + (size_t)rr * MM;
                    float bv = -1.f; int bi = MM;
                    for (int j = lane; j < MM; j += 32) {
                        bool tkn = (tk[j >> 5] >> (j & 31)) & 1u;
                        float x = tkn ? 0.f : row[j];
                        if (x > bv) { bv = x; bi = j; }
                    }
                    for (int off = 16; off; off >>= 1) {
                        float ov = __shfl_down_sync(FULLM, bv, off);
                        int   oi = __shfl_down_sync(FULLM, bi, off);
                        if (ov > bv || (ov == bv && oi < bi)) { bv = ov; bi = oi; }
                    }
                    float conf = __shfl_sync(FULLM, bv, 0);
                    int   ind  = __shfl_sync(FULLM, bi, 0);
                    if (lane == low) {
                        if (conf > MATCH_THR) {
                            int cur = memo_track[ind];
                            bool istr = cur > -1;
                            bool strong = (s_pk[rr] >> 1) & 1;
                            if (istr && strong) {
                                idv = cur;
                                tk[ind >> 5] |= 1u << (ind & 31);
                            } else idv = istr ? -1 : -2;
                        } else idv = -1;
                        done = true;
                    }
                    __syncwarp(FULLM);
                    unc2 = __ballot_sync(FULLM, !done);
                }
            }
            s_idv[r] = idv;
            __syncwarp(FULLM);
        }

        int num_tracks = *num_tracks_ptr;
        int carry = 0;
        for (int c2 = 0; c2 < ND / 32; c2++) {
            int r = c2 * 32 + lane;
            int idv = s_idv[r];
            int pk = s_pk[r];
            int vld = pk & 1;
            bool newt = (idv == -1) && ((pk >> 2) & 1) && vld;
            unsigned bm = __ballot_sync(FULLM, newt);
            int rank = __popc(bm & ((1u << lane) - 1u));
            if (newt) idv = num_tracks + carry + rank;
            carry += __popc(bm);
            int o = g_order[r];
            out[o] = (float)idv;
            out[ND + o] = vld ? 1.f : 0.f;
        }
    }
}

// ---------------- launch -----------------------------------------------------
extern "C" void kernel_launch(void* const* d_in, const int* in_sizes, int n_in,
                              void* d_out, int out_size) {
    (void)in_sizes; (void)n_in; (void)out_size;
    const float* det        = (const float*)d_in[0];
    const float* scores     = (const float*)d_in[1];
    const int*   cls        = (const int*)d_in[2];
    const float* emb        = (const float*)d_in[3];
    const float* memo_emb   = (const float*)d_in[4];
    const int*   memo_cls   = (const int*)d_in[5];
    const int*   memo_trk   = (const int*)d_in[6];
    const int*   num_tracks = (const int*)d_in[7];
    float* out = (float*)d_out;

    cudaFuncSetAttribute(greedy_kernel,
                         cudaFuncAttributeMaxDynamicSharedMemorySize,
                         GREEDY_SMEM);

    rank_kernel<<<ND / 256, 256>>>(scores);
    gather_kernel<<<ND, 256>>>(det, scores, cls, emb);
    nms_kernel<<<ND / 2, 256>>>();               // 4 subwarps per detection
    compact_kernel<<<1, 1024>>>();               // + fused embcompact
    sgemm_kernel<<<dim3(MM / BN, ND / BM), 256>>>(memo_emb);
    colmerge_kernel<<<MM / 256, 256>>>();
    simsrow_kernel<<<ND, 256>>>(memo_cls, out);
    greedy_kernel<<<1, 1024, GREEDY_SMEM>>>(memo_trk, num_tracks, out);
}

// round 17
// speedup vs baseline: 1.1096x; 1.1096x over previous
#include <cuda_runtime.h>
#include <cuda_bf16.h>
#include <math.h>
#include <stdint.h>

#define ND 4096
#define MM 8192
#define DE 256
#define TOPK 8
#define KEXT 768          // 3 limbs * 256

#define OBJ_THR   0.3f
#define INIT_THR  0.7f
#define MATCH_THR 0.5f
#define IOU_BACK  0.3f
#define IOU_CLASS 0.7f
#define CEXP      32.0f
#define FULLM     0xFFFFFFFFu

#define BM 128
#define NSEG (ND / BM)    // 32 block-rows max

// ---------------- scratch (device globals; no allocation allowed) ----------
static __device__ float          g_feats[(size_t)ND * MM];  // E = exp(f-32)
static __device__ __nv_bfloat16  g_Abf[(size_t)ND * KEXT];  // A' limbs (compact rows)
static __device__ __nv_bfloat16  g_Bbf[(size_t)MM * KEXT];  // B' limbs
static __device__ int      g_order[ND];
static __device__ float    g_scores_s[ND];
static __device__ int      g_cls_s[ND];
static __device__ float4   g_boxes_s[ND];
static __device__ float    g_area_s[ND];
static __device__ float    g_emb_s[ND * DE];
static __device__ int      g_bad[ND];
static __device__ int      g_valid[ND];
static __device__ int      g_vpos[ND];
static __device__ int      g_nvalid;
static __device__ float    g_colpart[NSEG][MM];
static __device__ float    g_colhalf[MM];
static __device__ float    g_topv[ND][TOPK];
static __device__ int      g_topi[ND][TOPK];

__device__ __forceinline__ uint32_t sptr(const void* p) {
    return (uint32_t)__cvta_generic_to_shared(p);
}
__device__ __forceinline__ unsigned short bf16bits(float x) {
    __nv_bfloat16 h = __float2bfloat16(x);
    return *(unsigned short*)&h;
}

// ---------------- 1. argsort(-scores): parallel rank-by-counting ------------
__global__ void rank_kernel(const float* __restrict__ scores) {
    __shared__ unsigned long long sk[ND];
    int t = threadIdx.x;
    int me = blockIdx.x * 256 + t;
    for (int i = t; i < ND; i += 256) {
        unsigned u = __float_as_uint(scores[i]);
        u ^= (u & 0x80000000u) ? 0xFFFFFFFFu : 0x80000000u;
        u = ~u;
        sk[i] = ((unsigned long long)u << 32) | (unsigned)i;
    }
    __syncthreads();
    unsigned long long mykey = sk[me];
    int rank = 0;
#pragma unroll 8
    for (int j = 0; j < ND; j++)
        rank += (sk[j] < mykey) ? 1 : 0;
    g_order[rank] = me;
}

// ---------------- 2. gather sorted views (+ areas) ---------------------------
__global__ void gather_kernel(const float* __restrict__ det,
                              const float* __restrict__ scores,
                              const int*   __restrict__ cls,
                              const float* __restrict__ emb) {
    int i = blockIdx.x;
    int o = g_order[i];
    if (threadIdx.x == 0) {
        g_scores_s[i] = scores[o];
        g_cls_s[i]    = cls[o];
        float4 b;
        b.x = det[o * 4 + 0]; b.y = det[o * 4 + 1];
        b.z = det[o * 4 + 2]; b.w = det[o * 4 + 3];
        g_boxes_s[i] = b;
        g_area_s[i] = fmaxf(b.z - b.x, 0.f) * fmaxf(b.w - b.y, 0.f);
    }
    for (int k = threadIdx.x; k < DE; k += blockDim.x)
        g_emb_s[i * DE + k] = emb[o * DE + k];
}

// ---------------- 3. NMS (R10): warp per det, 128 j's per ballot ------------
__global__ void nms_kernel() {
    int i = (blockIdx.x * blockDim.x + threadIdx.x) >> 5;
    int lane = threadIdx.x & 31;
    float4 bx = g_boxes_s[i];
    float  si = g_scores_s[i];
    float  thr = (si < OBJ_THR) ? IOU_BACK : IOU_CLASS;
    float  area_i = g_area_s[i];
    bool bad = false;
    for (int j0 = 0; j0 < i; j0 += 128) {
        bool ex = false;
#pragma unroll
        for (int u = 0; u < 4; u++) {
            int j = j0 + u * 32 + lane;
            if (j < i) {
                float4 bb = g_boxes_s[j];
                float  aj = g_area_s[j];
                float lx = fmaxf(bx.x, bb.x), ly = fmaxf(bx.y, bb.y);
                float rx = fminf(bx.z, bb.z), ry = fminf(bx.w, bb.w);
                float w = fmaxf(rx - lx, 0.f), h = fmaxf(ry - ly, 0.f);
                float inter = w * h;
                float denom = fmaxf(area_i + aj - inter, 1e-6f);
                ex |= (inter / denom > thr);   // exact division (reference semantics)
            }
        }
        if (__any_sync(FULLM, ex)) { bad = true; break; }
    }
    if (lane == 0) g_bad[i] = bad ? 1 : 0;
}

// ---------------- 4. compaction (R10 prefix sum) ----------------------------
__global__ void compact_kernel() {
    __shared__ int s[1024];
    int t = threadIdx.x;
    int v[4], cnt = 0;
#pragma unroll
    for (int k = 0; k < 4; k++) {
        v[k] = g_bad[t * 4 + k] ? 0 : 1;
        cnt += v[k];
    }
    s[t] = cnt;
    __syncthreads();
    for (int off = 1; off < 1024; off <<= 1) {
        int val = s[t];
        if (t >= off) val += s[t - off];
        __syncthreads();
        s[t] = val;
        __syncthreads();
    }
    int base = s[t] - cnt;
#pragma unroll
    for (int k = 0; k < 4; k++) {
        int i = t * 4 + k;
        g_valid[i] = v[k];
        g_vpos[i] = base;
        if (v[k]) base++;
    }
    if (t == 1023) g_nvalid = s[1023];
}

// ------ 5a. A limb conversion (compact rows): pattern [hi, lo, hi] ----------
__global__ void aconv_kernel() {
    int r = blockIdx.x;
    if (!g_valid[r]) return;
    int p = g_vpos[r];
    int t = threadIdx.x;                       // 128: 2 source cols each
    float2 x = *(const float2*)&g_emb_s[r * DE + t * 2];
    unsigned h0 = bf16bits(x.x);
    float f0; { __nv_bfloat16 hb = __float2bfloat16(x.x); f0 = __bfloat162float(hb); }
    unsigned l0 = bf16bits(x.x - f0);
    unsigned h1 = bf16bits(x.y);
    float f1; { __nv_bfloat16 hb = __float2bfloat16(x.y); f1 = __bfloat162float(hb); }
    unsigned l1 = bf16bits(x.y - f1);
    unsigned* dst = (unsigned*)&g_Abf[(size_t)p * KEXT + t * 6];
    dst[0] = h0 | (l0 << 16);   // cols: hi0, lo0
    dst[1] = h0 | (h1 << 16);   //       hi0, hi1
    dst[2] = l1 | (h1 << 16);   //       lo1, hi1
}

// ------ 5b. B limb conversion: pattern [hi, hi, lo] -------------------------
__global__ void bconv_kernel(const float* __restrict__ memo_emb) {
    int n = blockIdx.x;
    int t = threadIdx.x;                       // 128
    float2 x = *(const float2*)&memo_emb[(size_t)n * DE + t * 2];
    unsigned h0 = bf16bits(x.x);
    float f0; { __nv_bfloat16 hb = __float2bfloat16(x.x); f0 = __bfloat162float(hb); }
    unsigned l0 = bf16bits(x.x - f0);
    unsigned h1 = bf16bits(x.y);
    float f1; { __nv_bfloat16 hb = __float2bfloat16(x.y); f1 = __bfloat162float(hb); }
    unsigned l1 = bf16bits(x.y - f1);
    unsigned* dst = (unsigned*)&g_Bbf[(size_t)n * KEXT + t * 6];
    dst[0] = h0 | (h0 << 16);   // cols: hi0, hi0
    dst[1] = l0 | (h1 << 16);   //       lo0, hi1
    dst[2] = h1 | (l1 << 16);   //       hi1, lo1
}

// ------ 6. tensor-core GEMM (mma.sync bf16), E=exp epilogue + col partials --
__global__ void __launch_bounds__(256, 1) mma_kernel() {
    int nv = g_nvalid;
    int bm = blockIdx.y * BM;
    if (bm >= nv) return;
    int bn = blockIdx.x * 128;

    __shared__ __nv_bfloat16 As[128][40];     // 32 used + pad (80B row, 16B-aligned)
    __shared__ __nv_bfloat16 Bs[128][40];
    __shared__ float s_csum[2][128];

    int tid = threadIdx.x;
    int wid = tid >> 5, lane = tid & 31;
    int wm = wid & 1, wn = wid >> 1;          // warp tile 64x32

    float d[4][4][4];
#pragma unroll
    for (int a = 0; a < 4; a++)
#pragma unroll
        for (int b = 0; b < 4; b++)
#pragma unroll
            for (int c = 0; c < 4; c++) d[a][b][c] = 0.f;

    for (int kc = 0; kc < KEXT; kc += 32) {
        __syncthreads();
#pragma unroll
        for (int l = 0; l < 2; l++) {
            int e = tid + l * 256;            // 0..511
            int row = e >> 2, c8 = (e & 3) * 8;
            *(uint4*)&As[row][c8] =
                *(const uint4*)&g_Abf[(size_t)(bm + row) * KEXT + kc + c8];
            *(uint4*)&Bs[row][c8] =
                *(const uint4*)&g_Bbf[(size_t)(bn + row) * KEXT + kc + c8];
        }
        __syncthreads();
#pragma unroll
        for (int ks = 0; ks < 2; ks++) {
            uint32_t a[4][4], b[4][2];
            int arow = wm * 64 + (lane & 15);
            int acol = ks * 16 + (lane >> 4) * 8;
#pragma unroll
            for (int fm = 0; fm < 4; fm++) {
                uint32_t addr = sptr(&As[arow + fm * 16][acol]);
                asm volatile(
                    "ldmatrix.sync.aligned.m8n8.x4.shared.b16 {%0,%1,%2,%3}, [%4];"
                    : "=r"(a[fm][0]), "=r"(a[fm][1]), "=r"(a[fm][2]), "=r"(a[fm][3])
                    : "r"(addr));
            }
            // B is n-major ([n][k]) -> NON-trans ldmatrix gives the row.col
            // B fragment directly (k-consecutive pairs at fixed n).
            int brow = wn * 32 + (lane & 7);
            int bcol = ks * 16 + ((lane >> 3) & 1) * 8;
#pragma unroll
            for (int fn = 0; fn < 4; fn++) {
                uint32_t addr = sptr(&Bs[brow + fn * 8][bcol]);
                asm volatile(
                    "ldmatrix.sync.aligned.m8n8.x2.shared.b16 {%0,%1}, [%2];"
                    : "=r"(b[fn][0]), "=r"(b[fn][1])
                    : "r"(addr));
            }
#pragma unroll
            for (int fm = 0; fm < 4; fm++)
#pragma unroll
                for (int fn = 0; fn < 4; fn++) {
                    asm volatile(
                        "mma.sync.aligned.m16n8k16.row.col.f32.bf16.bf16.f32 "
                        "{%0,%1,%2,%3}, {%4,%5,%6,%7}, {%8,%9}, {%0,%1,%2,%3};"
                        : "+f"(d[fm][fn][0]), "+f"(d[fm][fn][1]),
                          "+f"(d[fm][fn][2]), "+f"(d[fm][fn][3])
                        : "r"(a[fm][0]), "r"(a[fm][1]), "r"(a[fm][2]), "r"(a[fm][3]),
                          "r"(b[fn][0]), "r"(b[fn][1]));
                }
        }
    }

    // epilogue: E = exp(f - 32), store, column partial sums (valid rows only)
    s_csum[tid >> 7][tid & 127] = 0.f;
    __syncthreads();

    float ps[4][2];
#pragma unroll
    for (int fn = 0; fn < 4; fn++) { ps[fn][0] = 0.f; ps[fn][1] = 0.f; }

#pragma unroll
    for (int fm = 0; fm < 4; fm++) {
        int gr0 = bm + wm * 64 + fm * 16 + (lane >> 2);
        int gr1 = gr0 + 8;
#pragma unroll
        for (int fn = 0; fn < 4; fn++) {
            int lc = wn * 32 + fn * 8 + (lane & 3) * 2;
            float e0 = __expf(d[fm][fn][0] - CEXP);
            float e1 = __expf(d[fm][fn][1] - CEXP);
            float e2 = __expf(d[fm][fn][2] - CEXP);
            float e3 = __expf(d[fm][fn][3] - CEXP);
            *(float2*)&g_feats[(size_t)gr0 * MM + bn + lc] = make_float2(e0, e1);
            *(float2*)&g_feats[(size_t)gr1 * MM + bn + lc] = make_float2(e2, e3);
            ps[fn][0] += (gr0 < nv ? e0 : 0.f) + (gr1 < nv ? e2 : 0.f);
            ps[fn][1] += (gr0 < nv ? e1 : 0.f) + (gr1 < nv ? e3 : 0.f);
        }
    }
#pragma unroll
    for (int fn = 0; fn < 4; fn++)
#pragma unroll
        for (int e = 0; e < 2; e++) {
            float v = ps[fn][e];
            v += __shfl_down_sync(FULLM, v, 16);
            v += __shfl_down_sync(FULLM, v, 8);
            v += __shfl_down_sync(FULLM, v, 4);
            ps[fn][e] = v;
        }
    if (lane < 4) {
#pragma unroll
        for (int fn = 0; fn < 4; fn++)
#pragma unroll
            for (int e = 0; e < 2; e++)
                s_csum[wm][wn * 32 + fn * 8 + lane * 2 + e] = ps[fn][e];
    }
    __syncthreads();
    if (tid < 128)
        g_colpart[blockIdx.y][bn + tid] = s_csum[0][tid] + s_csum[1][tid];
}

// ---------------- 7. merge column partials ----------------------------------
__global__ void colmerge_kernel() {
    int c = blockIdx.x * 256 + threadIdx.x;
    int nseg = (g_nvalid + BM - 1) / BM;
    float s = 0.f;
    for (int seg = 0; seg < nseg; seg++) s += g_colpart[seg][c];
    g_colhalf[c] = 0.5f / s;
}

// ---------------- 8. sims + row sum + top-8 (R10) ----------------------------
__global__ void simsrow_kernel(const int* __restrict__ memo_cls,
                               float* __restrict__ out) {
    __shared__ float srow[MM];
    __shared__ float s_red[256];
    __shared__ int   s_ri[256];
    __shared__ float sv[9 * 256];
    __shared__ int   si[9 * 256];
    int r = blockIdx.x, t = threadIdx.x;
    float* orow = out + 2 * ND + (size_t)r * MM;
    if (!g_valid[r]) {
        float4 z = make_float4(0.f, 0.f, 0.f, 0.f);
        float4* o4 = (float4*)orow;
        for (int j = t; j < MM / 4; j += 256) o4[j] = z;
        if (t < TOPK) { g_topv[r][t] = 0.f; g_topi[r][t] = 0; }
        return;
    }
    int v = g_vpos[r];
    const float4* f4 = (const float4*)(g_feats + (size_t)v * MM);
    float p0 = 0.f, p1 = 0.f;
#pragma unroll
    for (int it = 0; it < 8; it++) {
        int idx = t + it * 256;
        float4 x = f4[idx];
        ((float4*)srow)[idx] = x;
        p0 += x.x + x.z;
        p1 += x.y + x.w;
    }
    s_red[t] = p0 + p1;
    __syncthreads();
    for (int o = 128; o; o >>= 1) {
        if (t < o) s_red[t] += s_red[t + o];
        __syncthreads();
    }
    float hr = 0.5f / s_red[0];
    int clsr = g_cls_s[r];
    __syncthreads();

    float lv[9]; int li[9];
#pragma unroll
    for (int k = 0; k < 9; k++) { lv[k] = -1.f; li[k] = MM; }
    for (int j = t; j < MM; j += 256) {
        float E = srow[j];
        float hc = g_colhalf[j];
        float x = (memo_cls[j] == clsr) ? E * (hr + hc) : 0.f;
        orow[j] = x;
        if (x > lv[8]) {
            lv[8] = x; li[8] = j;
#pragma unroll
            for (int p = 8; p > 0; p--) {
                if (lv[p] > lv[p - 1]) {
                    float tv = lv[p]; lv[p] = lv[p - 1]; lv[p - 1] = tv;
                    int   tj = li[p]; li[p] = li[p - 1]; li[p - 1] = tj;
                }
            }
        }
    }
#pragma unroll
    for (int k = 0; k < 9; k++) { sv[k * 256 + t] = lv[k]; si[k * 256 + t] = li[k]; }
    __syncthreads();

    int h = 0;
    for (int k = 0; k < TOPK; k++) {
        float cv = (h < 9) ? sv[h * 256 + t] : -1.f;
        int   ci = (h < 9) ? si[h * 256 + t] : MM;
        s_red[t] = cv; s_ri[t] = ci;
        __syncthreads();
        for (int o = 128; o; o >>= 1) {
            if (t < o) {
                float ov = s_red[t + o]; int oi = s_ri[t + o];
                if (ov > s_red[t] || (ov == s_red[t] && oi < s_ri[t])) {
                    s_red[t] = ov; s_ri[t] = oi;
                }
            }
            __syncthreads();
        }
        float bv = s_red[0]; int bi = s_ri[0];
        if (t == 0) { g_topv[r][k] = bv; g_topi[r][k] = bi; }
        __syncthreads();
        if (cv == bv && ci == bi) h++;
    }
}

// -------- 9. greedy (R10): parallel prefetch + prefix-safe commits ----------
#define GREEDY_SMEM (ND * 8 * 4 + ND * 4 + (MM / 32) * 4 + ND * 2 + ND)

__global__ void greedy_kernel(const int* __restrict__ memo_track,
                              const int* __restrict__ num_tracks_ptr,
                              float* __restrict__ out) {
    extern __shared__ unsigned char dsm[];
    unsigned*       s_cand = (unsigned*)dsm;
    int*            s_idv  = (int*)(s_cand + ND * 8);
    unsigned*       tk     = (unsigned*)(s_idv + ND);
    unsigned short* s_pk   = (unsigned short*)(tk + MM / 32);
    unsigned char*  s_cnt  = (unsigned char*)(s_pk + ND);
    int t = threadIdx.x;

    for (int e = t; e < ND * 8; e += 1024) {
        int r = e >> 3, k = e & 7;
        float v = g_topv[r][k];
        unsigned w = 0xFFFFFFFFu;
        if (v > MATCH_THR) {
            int ind = g_topi[r][k];
            int trk = memo_track[ind];
            int it = (trk > -1) ? 1 : 0;
            w = (unsigned)ind | ((unsigned)it << 13) |
                ((unsigned)(it ? trk : 0) << 14);
        }
        s_cand[e] = w;
    }
    for (int i = t; i < MM / 32; i += 1024) tk[i] = 0u;
    for (int r = t; r < ND; r += 1024) {
        float sc = g_scores_s[r];
        s_pk[r] = (unsigned short)((g_valid[r] & 1) |
                  ((sc > OBJ_THR) ? 2 : 0) | ((sc > INIT_THR) ? 4 : 0));
        int c = 0;
        while (c < 8 && g_topv[r][c] > MATCH_THR) c++;
        s_cnt[r] = (unsigned char)c;
    }
    __syncthreads();

    if (t < 32) {
        int lane = t;
        const float* sims = out + 2 * ND;

        for (int cch = 0; cch < ND / 32; cch++) {
            int r = cch * 32 + lane;
            int cnt = s_cnt[r];
            int idx = 0;
            int idv = -1;
            bool done = (cnt == 0);

            while (true) {
                unsigned unc = __ballot_sync(FULLM, !done);
                if (!unc) break;

                int action = 0;
                int P = 0x4000 + lane;
                int myind = -1, mytid = 0, myit = 0;
                if (!done) {
                    while (idx < cnt) {
                        unsigned w = s_cand[r * 8 + idx];
                        int ind = (int)(w & 0x1FFFu);
                        if ((tk[ind >> 5] >> (ind & 31)) & 1u) idx++;
                        else {
                            myind = ind;
                            myit = (int)((w >> 13) & 1u);
                            mytid = (int)(w >> 14);
                            break;
                        }
                    }
                    if (idx >= cnt) {
                        if (cnt == 8) action = 4;
                        else { action = 1; idv = -1; }
                    } else {
                        P = myind;
                    }
                }
                unsigned grp = __match_any_sync(FULLM, P);
                unsigned pickm = __ballot_sync(FULLM, !done && action == 0);
                unsigned strongm = __ballot_sync(FULLM,
                                                 !done && ((s_pk[r] >> 1) & 1));
                if (!done && action == 0) {
                    if (!myit) { action = 1; idv = -2; }
                    else {
                        unsigned g = grp & pickm;
                        unsigned sg = g & strongm;
                        if (sg == 0) { action = 1; idv = -1; }
                        else {
                            int s = __ffs(sg) - 1;
                            if (lane < s)       { action = 1; idv = -1; }
                            else if (lane == s) { action = 2; idv = mytid; }
                            else                  action = 3;
                        }
                    }
                }
                unsigned deferm = __ballot_sync(FULLM,
                                                !done && (action == 3 || action == 4));
                int fb = deferm ? (__ffs(deferm) - 1) : 32;
                bool dep = (!done && (action == 1 || action == 2) &&
                            myind >= 0 && myit);
                if (dep && lane > fb) action = 3;

                if (!done && (action == 1 || action == 2)) {
                    if (action == 2)
                        atomicOr(&tk[myind >> 5], 1u << (myind & 31));
                    done = true;
                }
                __syncwarp(FULLM);

                unsigned unc2 = __ballot_sync(FULLM, !done);
                while (unc2) {
                    int low = __ffs(unc2) - 1;
                    int lact = __shfl_sync(FULLM, action, low);
                    if (lact != 4) break;
                    int rr = cch * 32 + low;
                    const float* row = sims + (size_t)rr * MM;
                    float bv = -1.f; int bi = MM;
                    for (int j = lane; j < MM; j += 32) {
                        bool tkn = (tk[j >> 5] >> (j & 31)) & 1u;
                        float x = tkn ? 0.f : row[j];
                        if (x > bv) { bv = x; bi = j; }
                    }
                    for (int off = 16; off; off >>= 1) {
                        float ov = __shfl_down_sync(FULLM, bv, off);
                        int   oi = __shfl_down_sync(FULLM, bi, off);
                        if (ov > bv || (ov == bv && oi < bi)) { bv = ov; bi = oi; }
                    }
                    float conf = __shfl_sync(FULLM, bv, 0);
                    int   ind  = __shfl_sync(FULLM, bi, 0);
                    if (lane == low) {
                        if (conf > MATCH_THR) {
                            int cur = memo_track[ind];
                            bool istr = cur > -1;
                            bool strong = (s_pk[rr] >> 1) & 1;
                            if (istr && strong) {
                                idv = cur;
                                tk[ind >> 5] |= 1u << (ind & 31);
                            } else idv = istr ? -1 : -2;
                        } else idv = -1;
                        done = true;
                    }
                    __syncwarp(FULLM);
                    unc2 = __ballot_sync(FULLM, !done);
                }
            }
            s_idv[r] = idv;
            __syncwarp(FULLM);
        }

        int num_tracks = *num_tracks_ptr;
        int carry = 0;
        for (int c2 = 0; c2 < ND / 32; c2++) {
            int r = c2 * 32 + lane;
            int idv = s_idv[r];
            int pk = s_pk[r];
            int vld = pk & 1;
            bool newt = (idv == -1) && ((pk >> 2) & 1) && vld;
            unsigned bm = __ballot_sync(FULLM, newt);
            int rank = __popc(bm & ((1u << lane) - 1u));
            if (newt) idv = num_tracks + carry + rank;
            carry += __popc(bm);
            int o = g_order[r];
            out[o] = (float)idv;
            out[ND + o] = vld ? 1.f : 0.f;
        }
    }
}

// ---------------- launch -----------------------------------------------------
extern "C" void kernel_launch(void* const* d_in, const int* in_sizes, int n_in,
                              void* d_out, int out_size) {
    (void)in_sizes; (void)n_in; (void)out_size;
    const float* det        = (const float*)d_in[0];
    const float* scores     = (const float*)d_in[1];
    const int*   cls        = (const int*)d_in[2];
    const float* emb        = (const float*)d_in[3];
    const float* memo_emb   = (const float*)d_in[4];
    const int*   memo_cls   = (const int*)d_in[5];
    const int*   memo_trk   = (const int*)d_in[6];
    const int*   num_tracks = (const int*)d_in[7];
    float* out = (float*)d_out;

    cudaFuncSetAttribute(greedy_kernel,
                         cudaFuncAttributeMaxDynamicSharedMemorySize,
                         GREEDY_SMEM);

    bconv_kernel<<<MM, 128>>>(memo_emb);          // independent of det chain
    rank_kernel<<<ND / 256, 256>>>(scores);
    gather_kernel<<<ND, 256>>>(det, scores, cls, emb);
    nms_kernel<<<ND / 8, 256>>>();
    compact_kernel<<<1, 1024>>>();
    aconv_kernel<<<ND, 128>>>();
    mma_kernel<<<dim3(MM / 128, ND / BM), 256>>>();
    colmerge_kernel<<<MM / 256, 256>>>();
    simsrow_kernel<<<ND, 256>>>(memo_cls, out);
    greedy_kernel<<<1, 1024, GREEDY_SMEM>>>(memo_trk, num_tracks, out);
}